// round 3
// baseline (speedup 1.0000x reference)
#include <cuda_runtime.h>

// Reference reduces to: y[b,c] = b_fc[c] + sum_o W_fc[c,o] * dot(h[b,0,:], W_emb[o,:])
// (the TreeLSTM scan result is deleted; adj and recurrent weights are dead).
// B=32, N=128, FI=768, FO=128.

#define B_  32
#define N_  128
#define FI_ 768
#define FO_ 128
#define NT_ 1024   // 32 warps per block

__global__ __launch_bounds__(NT_, 1)
void rvnn_head_kernel(const float* __restrict__ h,      // [B,N,FI]
                      const float* __restrict__ W_emb,  // [FO,FI]
                      const float* __restrict__ W_fc,   // [2,FO]
                      const float* __restrict__ b_fc,   // [2]
                      float* __restrict__ y)            // [B,2]
{
    const int b    = blockIdx.x;
    const int tid  = threadIdx.x;
    const int warp = tid >> 5;
    const int lane = tid & 31;

    __shared__ float s0[FO_], s1[FO_];

    // Direct register load of h[b,0,:] — coalesced per warp, identical
    // addresses across warps (L1 broadcast after first touch). No smem,
    // no barrier on the critical path.
    const float4* hrow = reinterpret_cast<const float4*>(h + (size_t)b * N_ * FI_);
    float4 hv[6];
    #pragma unroll
    for (int i = 0; i < 6; ++i)
        hv[i] = __ldg(&hrow[i * 32 + lane]);

    // 4 rows per warp: o = pass*32 + warp. All W loads are independent of
    // the h loads, so ~30 LDG.128 are in flight concurrently (MLP >> 1).
    float acc[4];
    #pragma unroll
    for (int pass = 0; pass < 4; ++pass) {
        const int o = pass * 32 + warp;
        const float4* wrow = reinterpret_cast<const float4*>(W_emb + (size_t)o * FI_);
        float a = 0.0f;
        #pragma unroll
        for (int i = 0; i < 6; ++i) {
            float4 wv = __ldg(&wrow[i * 32 + lane]);
            a = fmaf(hv[i].x, wv.x, a);
            a = fmaf(hv[i].y, wv.y, a);
            a = fmaf(hv[i].z, wv.z, a);
            a = fmaf(hv[i].w, wv.w, a);
        }
        acc[pass] = a;
    }

    // Four independent warp reductions (pipeline through the shfl unit).
    #pragma unroll
    for (int pass = 0; pass < 4; ++pass) {
        float a = acc[pass];
        #pragma unroll
        for (int off = 16; off > 0; off >>= 1)
            a += __shfl_down_sync(0xffffffffu, a, off);
        if (lane == 0) {
            const int o = pass * 32 + warp;
            s0[o] = a * W_fc[o];          // W_fc row 0
            s1[o] = a * W_fc[FO_ + o];    // W_fc row 1
        }
    }
    __syncthreads();

    // Final 128-element contraction by warp 0.
    if (warp == 0) {
        float a0 = s0[lane] + s0[lane + 32] + s0[lane + 64] + s0[lane + 96];
        float a1 = s1[lane] + s1[lane + 32] + s1[lane + 64] + s1[lane + 96];
        #pragma unroll
        for (int off = 16; off > 0; off >>= 1) {
            a0 += __shfl_down_sync(0xffffffffu, a0, off);
            a1 += __shfl_down_sync(0xffffffffu, a1, off);
        }
        if (lane == 0) {
            y[b * 2 + 0] = a0 + b_fc[0];
            y[b * 2 + 1] = a1 + b_fc[1];
        }
    }
}

extern "C" void kernel_launch(void* const* d_in, const int* in_sizes, int n_in,
                              void* d_out, int out_size)
{
    // metadata order: h, adj, W_emb, W_ioux, b_ioux, W_iouh, b_iouh,
    //                 W_coux, b_coux, W_couh, b_couh, W_fc, b_fc
    const float* h     = (const float*)d_in[0];
    const float* W_emb = (const float*)d_in[2];
    const float* W_fc  = (const float*)d_in[11];
    const float* b_fc  = (const float*)d_in[12];
    float* y = (float*)d_out;

    rvnn_head_kernel<<<B_, NT_>>>(h, W_emb, W_fc, b_fc, y);
}

// round 4
// speedup vs baseline: 1.2977x; 1.2977x over previous
#include <cuda_runtime.h>

// y[b,c] = b_fc[c] + dot(h[b,0,:], V[c,:]),  V = W_fc @ W_emb  ([2,768])
// (TreeLSTM scan in the reference is dead code; adj and recurrent weights unused.)
// B=32, N=128, FI=768, FO=128.

#define B_  32
#define N_  128
#define FI_ 768
#define FO_ 128

__device__ float g_V[2][FI_];   // scratch: V = W_fc @ W_emb

// Kernel A: V[c,f] = sum_o W_fc[c,o] * W_emb[o,f]
// grid = 24 blocks x 128 threads. Block covers 32 f-columns; the 4 warps
// split the o-range (32 o's each). All W_emb loads are lane-consecutive in f
// (coalesced 128B) and mutually independent -> huge chip MLP, BW-limited.
__global__ __launch_bounds__(128, 1)
void rvnn_precompute_V(const float* __restrict__ W_emb,  // [FO,FI]
                       const float* __restrict__ W_fc)   // [2,FO]
{
    const int t  = threadIdx.x;
    const int fl = t & 31;        // f within block
    const int g  = t >> 5;        // o-chunk 0..3
    const int f  = blockIdx.x * 32 + fl;

    float a0 = 0.0f, a1 = 0.0f;
    #pragma unroll
    for (int j = 0; j < 32; ++j) {
        const int o = g * 32 + j;
        float w = __ldg(&W_emb[(size_t)o * FI_ + f]);      // coalesced across lanes
        a0 = fmaf(__ldg(&W_fc[o]),        w, a0);          // broadcast
        a1 = fmaf(__ldg(&W_fc[FO_ + o]),  w, a1);
    }

    __shared__ float sp0[4][32], sp1[4][32];
    sp0[g][fl] = a0;
    sp1[g][fl] = a1;
    __syncthreads();

    if (t < 32) {
        g_V[0][blockIdx.x * 32 + t] = sp0[0][t] + sp0[1][t] + sp0[2][t] + sp0[3][t];
    } else if (t < 64) {
        const int l = t - 32;
        g_V[1][blockIdx.x * 32 + l] = sp1[0][l] + sp1[1][l] + sp1[2][l] + sp1[3][l];
    }
}

// Kernel B: y[b,c] = b_fc[c] + dot(h[b,0,:], V[c,:])
// grid = 32 blocks x 192 threads (6 warps). One float4 chunk per thread,
// single load round, then warp shfl + tiny smem combine.
__global__ __launch_bounds__(192, 1)
void rvnn_head_kernel(const float* __restrict__ h,    // [B,N,FI]
                      const float* __restrict__ b_fc, // [2]
                      float* __restrict__ y)          // [B,2]
{
    const int b    = blockIdx.x;
    const int t    = threadIdx.x;           // 0..191
    const int warp = t >> 5;                // 0..5
    const int lane = t & 31;

    const float4* hrow = reinterpret_cast<const float4*>(h + (size_t)b * N_ * FI_);
    float4 hv = __ldg(&hrow[t]);
    float4 v0 = *reinterpret_cast<const float4*>(&g_V[0][t * 4]);
    float4 v1 = *reinterpret_cast<const float4*>(&g_V[1][t * 4]);

    float a0 = fmaf(hv.x, v0.x, fmaf(hv.y, v0.y, fmaf(hv.z, v0.z, hv.w * v0.w)));
    float a1 = fmaf(hv.x, v1.x, fmaf(hv.y, v1.y, fmaf(hv.z, v1.z, hv.w * v1.w)));

    #pragma unroll
    for (int off = 16; off > 0; off >>= 1) {
        a0 += __shfl_down_sync(0xffffffffu, a0, off);
        a1 += __shfl_down_sync(0xffffffffu, a1, off);
    }

    __shared__ float w0[6], w1[6];
    if (lane == 0) { w0[warp] = a0; w1[warp] = a1; }
    __syncthreads();

    if (t == 0) {
        float s0 = w0[0] + w0[1] + w0[2] + w0[3] + w0[4] + w0[5];
        float s1 = w1[0] + w1[1] + w1[2] + w1[3] + w1[4] + w1[5];
        y[b * 2 + 0] = s0 + b_fc[0];
        y[b * 2 + 1] = s1 + b_fc[1];
    }
}

extern "C" void kernel_launch(void* const* d_in, const int* in_sizes, int n_in,
                              void* d_out, int out_size)
{
    // metadata order: h, adj, W_emb, W_ioux, b_ioux, W_iouh, b_iouh,
    //                 W_coux, b_coux, W_couh, b_couh, W_fc, b_fc
    const float* h     = (const float*)d_in[0];
    const float* W_emb = (const float*)d_in[2];
    const float* W_fc  = (const float*)d_in[11];
    const float* b_fc  = (const float*)d_in[12];
    float* y = (float*)d_out;

    rvnn_precompute_V<<<FI_ / 32, 128>>>(W_emb, W_fc);
    rvnn_head_kernel<<<B_, 192>>>(h, b_fc, y);
}